// round 12
// baseline (speedup 1.0000x reference)
#include <cuda_runtime.h>
#include <math_constants.h>

// Problem constants
#define KS     7
#define HALF   3
#define B_DIM  32
#define C_DIM  64
#define L_DIM  4096
#define I_DIM  (L_DIM / 2)        // 2048 outputs per row
#define ROWS_PER_BLK 8
#define NBLK   (B_DIM * C_DIM / ROWS_PER_BLK)   // 256
#define NTHREADS 256

// Block table range: k in [s0, s0 + 7 + 2*2047] -> 4102 entries
#define E_N    4102
// 8-entry chunks
#define NCHUNK ((E_N + 7) / 8)    // 513

// Padded smem index: stride-8 gather reads hit 32 distinct banks.
#define PD(e) ((e) + ((e) >> 5))

// ---------------------------------------------------------------------------
// Single kernel, no inter-block deps, ONE barrier. Block q owns rows
// 8q..8q+7 (b = q>>3, c_base = (q&7)*8, s0 = b + c_base <= 87).
// out[row, i] = dil(s + 2i); valid tap z of dil(k) = f_flat[k+z] + h[c',z],
// h[c',z] = -(z^2)/(4*t[c']), c' = k>>12, validity 0 <= (k&4095)+z < L.
// Compute reads f windows directly from GMEM (L2-hot, 16KB region).
// ---------------------------------------------------------------------------
__global__ void __launch_bounds__(NTHREADS) pp_kernel(
        const float* __restrict__ f,
        const float* __restrict__ t,
        float4* __restrict__ out) {
    __shared__ float dwin[PD(E_N - 1) + 16];

    const int tid = threadIdx.x;
    const int q   = blockIdx.x;
    const int s0  = (q >> 3) + ((q & 7) << 3);   // b + c_base, <= 87

    // ---- Hoisted h values (same rounding as reference: -(z^2)/(4t)) ----
    const float d0 = 4.0f * __ldg(&t[0]);
    const float d1 = 4.0f * __ldg(&t[1]);
    const float h1c[2] = { -1.0f / d0, -1.0f / d1 };
    const float h4c[2] = { -4.0f / d0, -4.0f / d1 };
    const float h9c[2] = { -9.0f / d0, -9.0f / d1 };

    // ---- Dilation window: 8-entry chunks straight from GMEM ----
    for (int ch = tid; ch < NCHUNK; ch += NTHREADS) {
        const int e0  = ch << 3;
        const int k0  = s0 + e0;
        const int l0f = k0 & (L_DIM - 1);
        const bool interior = (l0f >= HALF) && (l0f <= L_DIM - 4 - 7)
                              && (e0 + 7 < E_N);

        if (interior) {
            const int c1 = (k0 >> 12) & 1;
            const float h1 = h1c[c1], h4 = h4c[c1], h9 = h9c[c1];
            // v[x] = f_flat[k0 - 3 + x], x = 0..13 ; entry j taps v[j..j+6]
            float v[14];
            const float* __restrict__ w = f + (k0 - HALF);
            #pragma unroll
            for (int x = 0; x < 14; ++x)
                v[x] = __ldg(&w[x]);
            #pragma unroll
            for (int j = 0; j < 8; ++j) {
                float mx1 = fmaxf(v[j + 2], v[j + 4]);
                float mx4 = fmaxf(v[j + 1], v[j + 5]);
                float mx9 = fmaxf(v[j],     v[j + 6]);
                float m = fmaxf(fmaxf(v[j + 3], mx1 + h1),
                                fmaxf(mx4 + h4, mx9 + h9));
                dwin[PD(e0 + j)] = m;
            }
        } else {
            // Border / tail chunk: fully predicated per entry (rare)
            #pragma unroll
            for (int j = 0; j < 8; ++j) {
                int e = e0 + j;
                if (e >= E_N) break;
                int k  = s0 + e;
                int l0 = k & (L_DIM - 1);
                int c1 = (k >> 12) & 1;
                float h1 = h1c[c1], h4 = h4c[c1], h9 = h9c[c1];
                float m = __ldg(&f[k]);
                m = fmaxf(m, (l0 >= 1)        ? __ldg(&f[k - 1]) + h1 : -CUDART_INF_F);
                m = fmaxf(m, (l0 < L_DIM - 1) ? __ldg(&f[k + 1]) + h1 : -CUDART_INF_F);
                m = fmaxf(m, (l0 >= 2)        ? __ldg(&f[k - 2]) + h4 : -CUDART_INF_F);
                m = fmaxf(m, (l0 < L_DIM - 2) ? __ldg(&f[k + 2]) + h4 : -CUDART_INF_F);
                m = fmaxf(m, (l0 >= 3)        ? __ldg(&f[k - 3]) + h9 : -CUDART_INF_F);
                m = fmaxf(m, (l0 < L_DIM - 3) ? __ldg(&f[k + 3]) + h9 : -CUDART_INF_F);
                dwin[PD(e)] = m;
            }
        }
    }

    __syncthreads();

    // ---- Emit 8 rows x 512 float4 (4096 float4/block, 16 per thread) ----
    float4* __restrict__ oblk = out + (q << 3) * (I_DIM / 4);
    #pragma unroll
    for (int w = 0; w < 16; ++w) {
        int u  = w * NTHREADS + tid;             // 0..4095
        int rr = u >> 9;                         // local row 0..7
        int i4 = u & (I_DIM / 4 - 1);            // float4 index in row
        int e0 = rr + (i4 << 3);                 // element e for i = 4*i4
        float4 r;
        r.x = dwin[PD(e0)];
        r.y = dwin[PD(e0 + 2)];
        r.z = dwin[PD(e0 + 4)];
        r.w = dwin[PD(e0 + 6)];
        oblk[rr * (I_DIM / 4) + i4] = r;
    }
}

extern "C" void kernel_launch(void* const* d_in, const int* in_sizes, int n_in,
                              void* d_out, int out_size) {
    const float* f = (const float*)d_in[0];   // [32, 64, 4096] float32
    const float* t = (const float*)d_in[1];   // [64] float32
    float4* out = (float4*)d_out;             // [32, 64, 2048] float32

    pp_kernel<<<NBLK, NTHREADS>>>(f, t, out);
}

// round 15
// speedup vs baseline: 1.2294x; 1.2294x over previous
#include <cuda_runtime.h>
#include <math_constants.h>

// Problem constants
#define KS     7
#define HALF   3
#define B_DIM  32
#define C_DIM  64
#define L_DIM  4096
#define I_DIM  (L_DIM / 2)        // 2048 outputs per row
#define I4_DIM (I_DIM / 4)        // 512 float4 per row

// Block decomposition: 128 rowgroups (16 rows each) x 4 i-quarters
#define RG_ROWS   16
#define NSPLIT    4
#define NBLK      ((B_DIM * C_DIM / RG_ROWS) * NSPLIT)   // 512
#define NTHREADS  256
#define J4_N      (I4_DIM / NSPLIT)    // 128 float4 per row per block

// Per-block table slice: e = rr + 8*j4 + 2c, max 15 + 1016 + 6 = 1037
#define E_N    1038
#define F_N    (E_N + 6)          // staged f window: f_flat[kbase-3 .. kbase+E_N+2]
#define NCHUNK ((E_N + 7) / 8)    // 130

// Padded smem index: stride-8 gather reads hit 32 distinct banks.
#define PD(e) ((e) + ((e) >> 5))

// ---------------------------------------------------------------------------
// Block id q = g * NSPLIT + h: rowgroup g (rows 16g..16g+15; b = g>>2,
// c_base = (g&3)*16, s0 = b + c_base <= 79), i-quarter h (i4 in
// [128h, 128h+127]).  kbase = s0 + 1024h.  out[row,i] = dil(s + 2i);
// valid tap z of dil(k) = f_flat[k+z] + h[c',z], h[c',z] = -(z^2)/(4 t[c']),
// c' = k>>12, validity 0 <= (k&4095)+z < L.
// ---------------------------------------------------------------------------
__global__ void __launch_bounds__(NTHREADS) pp_kernel(
        const float* __restrict__ f,
        const float* __restrict__ t,
        float4* __restrict__ out) {
    __shared__ __align__(16) float fwin[F_N];
    __shared__ float dwin[PD(E_N - 1) + 16];

    const int tid = threadIdx.x;
    const int g   = blockIdx.x >> 2;             // rowgroup
    const int h   = blockIdx.x & 3;              // i-quarter
    const int s0  = (g >> 2) + ((g & 3) << 4);   // b + c_base, <= 79
    const int kbase = s0 + (h << 10);            // <= 79 + 3072

    // ---- Stage f window (coalesced; low-edge guard only) ----
    #pragma unroll
    for (int x = tid; x < F_N; x += NTHREADS) {
        int gi = kbase - 3 + x;                  // max <= 4191, in-bounds
        fwin[x] = (gi >= 0) ? __ldg(&f[gi]) : 0.0f;
    }

    // ---- Hoisted h values (same rounding as reference: -(z^2)/(4t)) ----
    const float d0 = 4.0f * __ldg(&t[0]);
    const float d1 = 4.0f * __ldg(&t[1]);
    const float h1c[2] = { -1.0f / d0, -1.0f / d1 };
    const float h4c[2] = { -4.0f / d0, -4.0f / d1 };
    const float h9c[2] = { -9.0f / d0, -9.0f / d1 };

    __syncthreads();

    // ---- Dilation slice: 8-entry chunks (<= 1 per thread) ----
    for (int ch = tid; ch < NCHUNK; ch += NTHREADS) {
        const int e0  = ch << 3;
        const int k0  = kbase + e0;
        const int l0f = k0 & (L_DIM - 1);
        const bool interior = (l0f >= HALF) && (l0f <= L_DIM - 4 - 7)
                              && (e0 + 7 < E_N);

        if (interior) {
            const int c1 = (k0 >> 12) & 1;
            const float h1 = h1c[c1], h4 = h4c[c1], h9 = h9c[c1];
            // v[x] = fwin[e0 + x], x = 0..13 ; entry j taps v[j..j+6]
            float v[14];
            float4 a = *reinterpret_cast<const float4*>(&fwin[e0]);
            float4 b = *reinterpret_cast<const float4*>(&fwin[e0 + 4]);
            float4 c = *reinterpret_cast<const float4*>(&fwin[e0 + 8]);
            float2 d = *reinterpret_cast<const float2*>(&fwin[e0 + 12]);
            v[0]=a.x; v[1]=a.y; v[2]=a.z; v[3]=a.w;
            v[4]=b.x; v[5]=b.y; v[6]=b.z; v[7]=b.w;
            v[8]=c.x; v[9]=c.y; v[10]=c.z; v[11]=c.w;
            v[12]=d.x; v[13]=d.y;
            #pragma unroll
            for (int j = 0; j < 8; ++j) {
                float mx1 = fmaxf(v[j + 2], v[j + 4]);
                float mx4 = fmaxf(v[j + 1], v[j + 5]);
                float mx9 = fmaxf(v[j],     v[j + 6]);
                float m = fmaxf(fmaxf(v[j + 3], mx1 + h1),
                                fmaxf(mx4 + h4, mx9 + h9));
                dwin[PD(e0 + j)] = m;
            }
        } else {
            // Border / tail chunk: fully predicated per entry (rare)
            #pragma unroll
            for (int j = 0; j < 8; ++j) {
                int e = e0 + j;
                if (e >= E_N) break;
                int k  = kbase + e;
                int l0 = k & (L_DIM - 1);
                int c1 = (k >> 12) & 1;
                float h1 = h1c[c1], h4 = h4c[c1], h9 = h9c[c1];
                const float* w = &fwin[e + HALF];
                float m = w[0];
                m = fmaxf(m, (l0 >= 1)        ? w[-1] + h1 : -CUDART_INF_F);
                m = fmaxf(m, (l0 < L_DIM - 1) ? w[ 1] + h1 : -CUDART_INF_F);
                m = fmaxf(m, (l0 >= 2)        ? w[-2] + h4 : -CUDART_INF_F);
                m = fmaxf(m, (l0 < L_DIM - 2) ? w[ 2] + h4 : -CUDART_INF_F);
                m = fmaxf(m, (l0 >= 3)        ? w[-3] + h9 : -CUDART_INF_F);
                m = fmaxf(m, (l0 < L_DIM - 3) ? w[ 3] + h9 : -CUDART_INF_F);
                dwin[PD(e)] = m;
            }
        }
    }

    __syncthreads();

    // ---- Emit 16 rows x 128 float4 (2048 float4/block, 8 per thread) ----
    // Element for row rr, local quarter-index j4: e = rr + 8*j4.
    #pragma unroll
    for (int w = 0; w < 8; ++w) {
        int u  = w * NTHREADS + tid;             // 0..2047
        int rr = u >> 7;                         // local row 0..15
        int j4 = u & (J4_N - 1);                 // 0..127
        int e0 = rr + (j4 << 3);
        float4 r;
        r.x = dwin[PD(e0)];
        r.y = dwin[PD(e0 + 2)];
        r.z = dwin[PD(e0 + 4)];
        r.w = dwin[PD(e0 + 6)];
        out[((g << 4) + rr) * I4_DIM + (h << 7) + j4] = r;
    }
}

extern "C" void kernel_launch(void* const* d_in, const int* in_sizes, int n_in,
                              void* d_out, int out_size) {
    const float* f = (const float*)d_in[0];   // [32, 64, 4096] float32
    const float* t = (const float*)d_in[1];   // [64] float32
    float4* out = (float4*)d_out;             // [32, 64, 2048] float32

    pp_kernel<<<NBLK, NTHREADS>>>(f, t, out);
}

// round 17
// speedup vs baseline: 1.2610x; 1.0257x over previous
#include <cuda_runtime.h>
#include <math_constants.h>

// Problem constants
#define KS     7
#define HALF   3
#define B_DIM  32
#define C_DIM  64
#define L_DIM  4096
#define I_DIM  (L_DIM / 2)        // 2048 outputs per row
#define I4_DIM (I_DIM / 4)        // 512 float4 per row

// Block decomposition: 128 rowgroups (16 rows each) x 8 i-eighths
#define RG_ROWS   16
#define NSPLIT    8
#define NBLK      ((B_DIM * C_DIM / RG_ROWS) * NSPLIT)   // 1024
#define NTHREADS  128
#define J4_N      (I4_DIM / NSPLIT)    // 64 float4 per row per block

// Per-block table slice: e = rr + 8*j4 + 2c, max 15 + 8*63 + 6 = 525
#define E_N    526
#define F_N    (E_N + 6)          // staged f: f_flat[kbase-3 .. kbase+E_N+2]
#define NCHUNK ((E_N + 7) / 8)    // 66

// Padded smem index: stride-8 gather reads hit 32 distinct banks.
#define PD(e) ((e) + ((e) >> 5))

// ---------------------------------------------------------------------------
// Block id = g * NSPLIT + h: rowgroup g (rows 16g..16g+15; b = g>>2,
// c_base = (g&3)*16, s0 = b + c_base <= 79), i-eighth h (j4 local index,
// i4 = 64h + j4).  kbase = s0 + 512h.  out[row,i] = dil(s + 2i);
// valid tap z of dil(k) = f_flat[k+z] + h[c',z], h[c',z] = -(z^2)/(4 t[c']),
// c' = k>>12, validity 0 <= (k&4095)+z < L.
// ---------------------------------------------------------------------------
__global__ void __launch_bounds__(NTHREADS) pp_kernel(
        const float* __restrict__ f,
        const float* __restrict__ t,
        float4* __restrict__ out) {
    __shared__ __align__(16) float fwin[F_N];
    __shared__ float dwin[PD(E_N - 1) + 16];

    const int tid = threadIdx.x;
    const int g   = blockIdx.x >> 3;             // rowgroup
    const int h   = blockIdx.x & 7;              // i-eighth
    const int s0  = (g >> 2) + ((g & 3) << 4);   // b + c_base, <= 79
    const int kbase = s0 + (h << 9);             // <= 79 + 3584

    // ---- Stage f window (coalesced; low-edge guard only) ----
    #pragma unroll
    for (int x = tid; x < F_N; x += NTHREADS) {
        int gi = kbase - 3 + x;                  // max <= 4191, in-bounds
        fwin[x] = (gi >= 0) ? __ldg(&f[gi]) : 0.0f;
    }

    // ---- Hoisted h values (same rounding as reference: -(z^2)/(4t)) ----
    const float d0 = 4.0f * __ldg(&t[0]);
    const float d1 = 4.0f * __ldg(&t[1]);
    const float h1c[2] = { -1.0f / d0, -1.0f / d1 };
    const float h4c[2] = { -4.0f / d0, -4.0f / d1 };
    const float h9c[2] = { -9.0f / d0, -9.0f / d1 };

    __syncthreads();

    // ---- Dilation slice: 8-entry chunks (<= 1 per thread) ----
    for (int ch = tid; ch < NCHUNK; ch += NTHREADS) {
        const int e0  = ch << 3;
        const int k0  = kbase + e0;
        const int l0f = k0 & (L_DIM - 1);
        const bool interior = (l0f >= HALF) && (l0f <= L_DIM - 4 - 7)
                              && (e0 + 7 < E_N);

        if (interior) {
            const int c1 = (k0 >> 12) & 1;
            const float h1 = h1c[c1], h4 = h4c[c1], h9 = h9c[c1];
            // v[x] = fwin[e0 + x], x = 0..13 ; entry j taps v[j..j+6]
            float v[14];
            float4 a = *reinterpret_cast<const float4*>(&fwin[e0]);
            float4 b = *reinterpret_cast<const float4*>(&fwin[e0 + 4]);
            float4 c = *reinterpret_cast<const float4*>(&fwin[e0 + 8]);
            float2 d = *reinterpret_cast<const float2*>(&fwin[e0 + 12]);
            v[0]=a.x; v[1]=a.y; v[2]=a.z; v[3]=a.w;
            v[4]=b.x; v[5]=b.y; v[6]=b.z; v[7]=b.w;
            v[8]=c.x; v[9]=c.y; v[10]=c.z; v[11]=c.w;
            v[12]=d.x; v[13]=d.y;
            #pragma unroll
            for (int j = 0; j < 8; ++j) {
                float mx1 = fmaxf(v[j + 2], v[j + 4]);
                float mx4 = fmaxf(v[j + 1], v[j + 5]);
                float mx9 = fmaxf(v[j],     v[j + 6]);
                float m = fmaxf(fmaxf(v[j + 3], mx1 + h1),
                                fmaxf(mx4 + h4, mx9 + h9));
                dwin[PD(e0 + j)] = m;
            }
        } else {
            // Border / tail chunk: fully predicated per entry (rare)
            #pragma unroll
            for (int j = 0; j < 8; ++j) {
                int e = e0 + j;
                if (e >= E_N) break;
                int k  = kbase + e;
                int l0 = k & (L_DIM - 1);
                int c1 = (k >> 12) & 1;
                float h1 = h1c[c1], h4 = h4c[c1], h9 = h9c[c1];
                const float* w = &fwin[e + HALF];
                float m = w[0];
                m = fmaxf(m, (l0 >= 1)        ? w[-1] + h1 : -CUDART_INF_F);
                m = fmaxf(m, (l0 < L_DIM - 1) ? w[ 1] + h1 : -CUDART_INF_F);
                m = fmaxf(m, (l0 >= 2)        ? w[-2] + h4 : -CUDART_INF_F);
                m = fmaxf(m, (l0 < L_DIM - 2) ? w[ 2] + h4 : -CUDART_INF_F);
                m = fmaxf(m, (l0 >= 3)        ? w[-3] + h9 : -CUDART_INF_F);
                m = fmaxf(m, (l0 < L_DIM - 3) ? w[ 3] + h9 : -CUDART_INF_F);
                dwin[PD(e)] = m;
            }
        }
    }

    __syncthreads();

    // ---- Emit 16 rows x 64 float4 (1024 float4/block, 8 per thread) ----
    // Element for row rr, local index j4: e = rr + 8*j4.
    #pragma unroll
    for (int w = 0; w < 8; ++w) {
        int u  = w * NTHREADS + tid;             // 0..1023
        int rr = u >> 6;                         // local row 0..15
        int j4 = u & (J4_N - 1);                 // 0..63
        int e0 = rr + (j4 << 3);
        float4 r;
        r.x = dwin[PD(e0)];
        r.y = dwin[PD(e0 + 2)];
        r.z = dwin[PD(e0 + 4)];
        r.w = dwin[PD(e0 + 6)];
        out[((g << 4) + rr) * I4_DIM + (h << 6) + j4] = r;
    }
}

extern "C" void kernel_launch(void* const* d_in, const int* in_sizes, int n_in,
                              void* d_out, int out_size) {
    const float* f = (const float*)d_in[0];   // [32, 64, 4096] float32
    const float* t = (const float*)d_in[1];   // [64] float32
    float4* out = (float4*)d_out;             // [32, 64, 2048] float32

    pp_kernel<<<NBLK, NTHREADS>>>(f, t, out);
}